// round 1
// baseline (speedup 1.0000x reference)
#include <cuda_runtime.h>
#include <math.h>

// Problem constants
#define K_CODES   8192
#define D_DIM     32
#define CSTRIDE   36            // 32 values + bias + 3 pad -> 144B, 16B-aligned rows
#define N_ROWS    32768         // 32*1024
#define TILE      128           // codes per smem tile
#define NTHREADS  128
#define NBLOCKS   (N_ROWS / NTHREADS)   // 256

typedef unsigned long long ull;

// Scratch (no cudaMalloc allowed)
__device__ float g_codes[K_CODES * CSTRIDE];   // normalized codes + bias, padded
__device__ float g_partial[NBLOCKS];           // per-block loss partial sums

// ---- packed f32x2 helpers (sm_103a FFMA2 path) ----
static __device__ __forceinline__ ull pack2(float lo, float hi) {
    ull r; asm("mov.b64 %0, {%1, %2};" : "=l"(r) : "f"(lo), "f"(hi)); return r;
}
static __device__ __forceinline__ void unpack2(ull v, float& lo, float& hi) {
    asm("mov.b64 {%0, %1}, %2;" : "=f"(lo), "=f"(hi) : "l"(v));
}
static __device__ __forceinline__ ull ffma2(ull a, ull b, ull c) {
    ull d; asm("fma.rn.f32x2 %0, %1, %2, %3;" : "=l"(d) : "l"(a), "l"(b), "l"(c)); return d;
}
static __device__ __forceinline__ ull fadd2(ull a, ull b) {
    ull d; asm("add.rn.f32x2 %0, %1, %2;" : "=l"(d) : "l"(a), "l"(b)); return d;
}

// ---- Kernel 1: normalize embedding -> padded table with folded bias ----
__global__ void vq_prep_kernel(const float* __restrict__ emb) {
    int t = blockIdx.x * blockDim.x + threadIdx.x;
    if (t >= K_CODES) return;
    const float4* ep = reinterpret_cast<const float4*>(emb + t * D_DIM);
    float v[D_DIM];
    float ss = 0.0f;
#pragma unroll
    for (int i = 0; i < 8; ++i) {
        float4 q = ep[i];
        v[4*i+0] = q.x; v[4*i+1] = q.y; v[4*i+2] = q.z; v[4*i+3] = q.w;
        ss += q.x*q.x + q.y*q.y + q.z*q.z + q.w*q.w;
    }
    float inv = 1.0f / fmaxf(sqrtf(ss), 1e-12f);
    float* o = g_codes + t * CSTRIDE;
    float ss2 = 0.0f;
#pragma unroll
    for (int d = 0; d < D_DIM; ++d) {
        float x = v[d] * inv;
        o[d] = x;
        ss2 += x * x;
    }
    o[32] = -0.5f * ss2;   // bias: argmax(dot - 0.5*||en||^2) == argmin(dist)
    o[33] = 0.0f;
    o[34] = 0.0f;
    o[35] = 0.0f;
}

// ---- Kernel 2: main VQ sweep (one z-row per thread) ----
__global__ void __launch_bounds__(NTHREADS, 2)
vq_main_kernel(const float* __restrict__ z,
               float* __restrict__ zq_out,
               float* __restrict__ idx_out) {
    __shared__ __align__(16) float tile[TILE * CSTRIDE];   // 18432 B

    const int row = blockIdx.x * NTHREADS + threadIdx.x;   // < N_ROWS exactly

    // Load + normalize z row
    const float4* zp = reinterpret_cast<const float4*>(z + row * D_DIM);
    float zv[D_DIM];
    float ss = 0.0f;
#pragma unroll
    for (int i = 0; i < 8; ++i) {
        float4 q = zp[i];
        zv[4*i+0] = q.x; zv[4*i+1] = q.y; zv[4*i+2] = q.z; zv[4*i+3] = q.w;
        ss += q.x*q.x + q.y*q.y + q.z*q.z + q.w*q.w;
    }
    const float inv = 1.0f / fmaxf(sqrtf(ss), 1e-12f);

    ull zr[18];
#pragma unroll
    for (int i = 0; i < 16; ++i)
        zr[i] = pack2(zv[2*i] * inv, zv[2*i+1] * inv);
    zr[16] = pack2(1.0f, 0.0f);   // picks up the -0.5*||en||^2 bias
    zr[17] = 0;                   // zero pad pair

    float best = -1e30f;
    int   bidx = 0;

    for (int t0 = 0; t0 < K_CODES; t0 += TILE) {
        __syncthreads();
        // cooperative coalesced tile copy (float4)
        {
            const float4* src = reinterpret_cast<const float4*>(g_codes + t0 * CSTRIDE);
            float4* dst = reinterpret_cast<float4*>(tile);
#pragma unroll
            for (int i = threadIdx.x; i < (TILE * CSTRIDE) / 4; i += NTHREADS)
                dst[i] = src[i];
        }
        __syncthreads();

#pragma unroll 2
        for (int j = 0; j < TILE; ++j) {
            const ulonglong2* cp2 =
                reinterpret_cast<const ulonglong2*>(tile + j * CSTRIDE);
            ull a0 = 0, a1 = 0;
#pragma unroll
            for (int i = 0; i < 9; ++i) {
                ulonglong2 c = cp2[i];          // LDS.128 broadcast
                a0 = ffma2(zr[2*i],   c.x, a0);
                a1 = ffma2(zr[2*i+1], c.y, a1);
            }
            ull a = fadd2(a0, a1);
            float lo, hi; unpack2(a, lo, hi);
            float s = lo + hi;
            if (s > best) { best = s; bidx = t0 + j; }  // strict > keeps first index on ties
        }
    }

    // Write idx (as float per output dtype)
    idx_out[row] = (float)bidx;

    // z_q_out = normalized embedding[idx]; also accumulate loss term
    const float* e = g_codes + bidx * CSTRIDE;
    float lsum = 0.0f;
    float4* oq = reinterpret_cast<float4*>(zq_out + row * D_DIM);
#pragma unroll
    for (int i = 0; i < 8; ++i) {
        float q0 = e[4*i+0], q1 = e[4*i+1], q2 = e[4*i+2], q3 = e[4*i+3];
        float d0 = q0 - zv[4*i+0] * inv;
        float d1 = q1 - zv[4*i+1] * inv;
        float d2 = q2 - zv[4*i+2] * inv;
        float d3 = q3 - zv[4*i+3] * inv;
        lsum += d0*d0 + d1*d1 + d2*d2 + d3*d3;
        float4 o; o.x = q0; o.y = q1; o.z = q2; o.w = q3;
        oq[i] = o;
    }

    // Deterministic block reduction of loss partials (reuse tile smem)
    __syncthreads();
    tile[threadIdx.x] = lsum;
    __syncthreads();
#pragma unroll
    for (int s = NTHREADS / 2; s > 0; s >>= 1) {
        if (threadIdx.x < s) tile[threadIdx.x] += tile[threadIdx.x + s];
        __syncthreads();
    }
    if (threadIdx.x == 0) g_partial[blockIdx.x] = tile[0];
}

// ---- Kernel 3: deterministic serial finalize ----
__global__ void vq_finalize_kernel(float* __restrict__ loss_out) {
    if (threadIdx.x == 0 && blockIdx.x == 0) {
        float s = 0.0f;
        for (int i = 0; i < NBLOCKS; ++i) s += g_partial[i];
        loss_out[0] = 1.25f * s / (float)(N_ROWS * D_DIM);
    }
}

extern "C" void kernel_launch(void* const* d_in, const int* in_sizes, int n_in,
                              void* d_out, int out_size) {
    const float* z   = (const float*)d_in[0];   // [32,1024,32]
    const float* emb = (const float*)d_in[1];   // [8192,32]
    float* out = (float*)d_out;

    float* zq_out   = out;                       // 1048576 floats
    float* loss_out = out + (size_t)N_ROWS * D_DIM;      // 1 float
    float* idx_out  = loss_out + 1;              // 32768 floats

    vq_prep_kernel<<<(K_CODES + 255) / 256, 256>>>(emb);
    vq_main_kernel<<<NBLOCKS, NTHREADS>>>(z, zq_out, idx_out);
    vq_finalize_kernel<<<1, 32>>>(loss_out);
}

// round 3
// speedup vs baseline: 1.6557x; 1.6557x over previous
#include <cuda_runtime.h>
#include <cstdint>
#include <math.h>

// ---------------- problem constants ----------------
#define D_DIM     32
#define K_CODES   8192
#define N_ROWS    32768
#define ASTRIDE   40                 // 32 dims + col32=1/bias slot + pad, conflict-free
#define BSTRIDE   40
#define MROWS     128                // rows per CTA
#define GRID_MAIN (N_ROWS / MROWS)   // 256
#define NTHR      256                // 8 warps
#define SCODES    128                // codes per pipeline stage
#define NSTAGES   (K_CODES / SCODES) // 64
#define TILE_BYTES  (SCODES * BSTRIDE * 4)   // 20480 (one hi or lo tile)
#define STAGE_BYTES (2 * TILE_BYTES)         // 40960
#define SMEM_B      (2 * STAGE_BYTES)        // 81920 (2 stages)
#define SMEM_TOTAL  (SMEM_B + NTHR * 4)      // + loss reduce scratch

// ---------------- device globals (no cudaMalloc allowed) ----------------
__device__ __align__(1024) float g_ahi[N_ROWS * ASTRIDE];
__device__ __align__(1024) float g_alo[N_ROWS * ASTRIDE];
__device__ __align__(1024) float g_bhi[K_CODES * BSTRIDE];
__device__ __align__(1024) float g_blo[K_CODES * BSTRIDE];
__device__ __align__(16)   float g_codes_norm[K_CODES * D_DIM];
__device__ float g_partial[GRID_MAIN];

// ---------------- helpers ----------------
static __device__ __forceinline__ uint32_t smem_u32(const void* p) {
    uint32_t a;
    asm("{ .reg .u64 t; cvta.to.shared.u64 t, %1; cvt.u32.u64 %0, t; }" : "=r"(a) : "l"(p));
    return a;
}
static __device__ __forceinline__ float tf32_rna(float x) {
    unsigned u; asm("cvt.rna.tf32.f32 %0, %1;" : "=r"(u) : "f"(x));
    return __uint_as_float(u);
}
#define CP_ASYNC16(dst, src) \
    asm volatile("cp.async.cg.shared.global [%0], [%1], 16;" :: "r"(dst), "l"(src) : "memory")
#define CP_COMMIT() asm volatile("cp.async.commit_group;" ::: "memory")
#define CP_WAIT(n)  asm volatile("cp.async.wait_group %0;" :: "n"(n) : "memory")

static __device__ __forceinline__ void mma_tf32(float& c0, float& c1, float& c2, float& c3,
                                                uint32_t a0, uint32_t a1, uint32_t a2, uint32_t a3,
                                                uint32_t b0, uint32_t b1) {
    asm volatile("mma.sync.aligned.m16n8k8.row.col.f32.tf32.tf32.f32 "
                 "{%0,%1,%2,%3}, {%4,%5,%6,%7}, {%8,%9}, {%0,%1,%2,%3};"
                 : "+f"(c0), "+f"(c1), "+f"(c2), "+f"(c3)
                 : "r"(a0), "r"(a1), "r"(a2), "r"(a3), "r"(b0), "r"(b1));
}

// ---------------- prep: normalize z rows, tf32 split ----------------
__global__ void vq_prep_z(const float* __restrict__ z) {
    int row = blockIdx.x * blockDim.x + threadIdx.x;   // 32768 threads
    const float4* zp = reinterpret_cast<const float4*>(z + (size_t)row * D_DIM);
    float v[D_DIM]; float ss = 0.0f;
#pragma unroll
    for (int i = 0; i < 8; ++i) {
        float4 q = zp[i];
        v[4*i+0]=q.x; v[4*i+1]=q.y; v[4*i+2]=q.z; v[4*i+3]=q.w;
        ss += q.x*q.x + q.y*q.y + q.z*q.z + q.w*q.w;
    }
    float inv = 1.0f / fmaxf(sqrtf(ss), 1e-12f);
    float* ah = g_ahi + (size_t)row * ASTRIDE;
    float* al = g_alo + (size_t)row * ASTRIDE;
#pragma unroll
    for (int c = 0; c < D_DIM; ++c) {
        float x  = v[c] * inv;
        float hi = tf32_rna(x);
        ah[c] = hi;
        al[c] = tf32_rna(x - hi);
    }
    ah[32] = 1.0f; al[32] = 0.0f;              // bias pickup column
#pragma unroll
    for (int c = 33; c < ASTRIDE; ++c) { ah[c] = 0.0f; al[c] = 0.0f; }
}

// ---------------- prep: normalize codes, fold bias, tf32 split ----------------
__global__ void vq_prep_codes(const float* __restrict__ emb) {
    int t = blockIdx.x * blockDim.x + threadIdx.x;     // 8192 threads
    const float4* ep = reinterpret_cast<const float4*>(emb + (size_t)t * D_DIM);
    float v[D_DIM]; float ss = 0.0f;
#pragma unroll
    for (int i = 0; i < 8; ++i) {
        float4 q = ep[i];
        v[4*i+0]=q.x; v[4*i+1]=q.y; v[4*i+2]=q.z; v[4*i+3]=q.w;
        ss += q.x*q.x + q.y*q.y + q.z*q.z + q.w*q.w;
    }
    float inv = 1.0f / fmaxf(sqrtf(ss), 1e-12f);
    float* bh = g_bhi + (size_t)t * BSTRIDE;
    float* bl = g_blo + (size_t)t * BSTRIDE;
    float ss2 = 0.0f;
#pragma unroll
    for (int c = 0; c < D_DIM; ++c) {
        float x = v[c] * inv;
        g_codes_norm[(size_t)t * D_DIM + c] = x;
        ss2 += x * x;
        float hi = tf32_rna(x);
        bh[c] = hi;
        bl[c] = tf32_rna(x - hi);
    }
    float bias = -0.5f * ss2;                  // argmax(dot - 0.5||e||^2) == argmin dist
    float bias_hi = tf32_rna(bias);
    bh[32] = bias_hi;
    bl[32] = tf32_rna(bias - bias_hi);
#pragma unroll
    for (int c = 33; c < BSTRIDE; ++c) { bh[c] = 0.0f; bl[c] = 0.0f; }
}

// ---------------- main: 3xTF32 mma.sync GEMM + fused argmax ----------------
__global__ void __launch_bounds__(NTHR, 2)
vq_main(float* __restrict__ zq_out, float* __restrict__ idx_out) {
    extern __shared__ __align__(16) char smem[];
    const uint32_t sb = smem_u32(smem);
    const int tid = threadIdx.x;
    const int w   = tid >> 5;          // warp 0..7
    const int g   = (tid & 31) >> 2;   // group id 0..7
    const int tg  = tid & 3;           // thread-in-group 0..3
    const int rb  = blockIdx.x;

    // ---- load resident A fragments (z rows, hi 5 ksteps incl bias col, lo 4) ----
    const int r0 = rb * MROWS + w * 16 + g;
    const int r1 = r0 + 8;
    uint32_t ahi[5][4], alo[4][4];
    {
        const uint32_t* a0p = reinterpret_cast<const uint32_t*>(g_ahi + (size_t)r0 * ASTRIDE);
        const uint32_t* a1p = reinterpret_cast<const uint32_t*>(g_ahi + (size_t)r1 * ASTRIDE);
        const uint32_t* l0p = reinterpret_cast<const uint32_t*>(g_alo + (size_t)r0 * ASTRIDE);
        const uint32_t* l1p = reinterpret_cast<const uint32_t*>(g_alo + (size_t)r1 * ASTRIDE);
#pragma unroll
        for (int ks = 0; ks < 5; ++ks) {
            int c0 = ks * 8 + tg, c1 = c0 + 4;
            ahi[ks][0] = a0p[c0]; ahi[ks][1] = a1p[c0];
            ahi[ks][2] = a0p[c1]; ahi[ks][3] = a1p[c1];
        }
#pragma unroll
        for (int ks = 0; ks < 4; ++ks) {
            int c0 = ks * 8 + tg, c1 = c0 + 4;
            alo[ks][0] = l0p[c0]; alo[ks][1] = l1p[c0];
            alo[ks][2] = l0p[c1]; alo[ks][3] = l1p[c1];
        }
    }

    // ---- stage copy: 128 codes (hi + lo tiles) via cp.async ----
    auto stage_copy = [&](int t) {
        const int slot = t & 1;
        const float* srch = g_bhi + (size_t)t * SCODES * BSTRIDE;
        const float* srcl = g_blo + (size_t)t * SCODES * BSTRIDE;
        const uint32_t dsth = sb + slot * STAGE_BYTES;
        const uint32_t dstl = dsth + TILE_BYTES;
#pragma unroll
        for (int j = 0; j < 5; ++j) {               // 1280 16B units per tile / 256 thr
            int u = tid + j * NTHR;
            CP_ASYNC16(dsth + u * 16, srch + u * 4);
            CP_ASYNC16(dstl + u * 16, srcl + u * 4);
        }
        CP_COMMIT();
    };

    float best0 = -1e30f, best1 = -1e30f;
    int   bi0 = 0, bi1 = 0;

    stage_copy(0);
    for (int t = 0; t < NSTAGES; ++t) {
        if (t + 1 < NSTAGES) { stage_copy(t + 1); CP_WAIT(1); }
        else                 { CP_WAIT(0); }
        __syncthreads();

        const float* bh = reinterpret_cast<const float*>(smem + (t & 1) * STAGE_BYTES);
        const float* bl = reinterpret_cast<const float*>(smem + (t & 1) * STAGE_BYTES + TILE_BYTES);

#pragma unroll 2
        for (int ch = 0; ch < SCODES / 8; ++ch) {
            const uint32_t* bhp = reinterpret_cast<const uint32_t*>(bh + (ch * 8 + g) * BSTRIDE);
            const uint32_t* blp = reinterpret_cast<const uint32_t*>(bl + (ch * 8 + g) * BSTRIDE);
            uint32_t bhi[5][2], blo[5][2];
#pragma unroll
            for (int ks = 0; ks < 5; ++ks) {
                bhi[ks][0] = bhp[ks * 8 + tg];  bhi[ks][1] = bhp[ks * 8 + tg + 4];
                blo[ks][0] = blp[ks * 8 + tg];  blo[ks][1] = blp[ks * 8 + tg + 4];
            }
            float c0 = 0.f, c1 = 0.f, c2 = 0.f, c3 = 0.f;
            // pass 1: Ahi*Bhi (kstep4 adds bias_hi via A col32 = 1)
#pragma unroll
            for (int ks = 0; ks < 5; ++ks)
                mma_tf32(c0,c1,c2,c3, ahi[ks][0],ahi[ks][1],ahi[ks][2],ahi[ks][3],
                         bhi[ks][0], bhi[ks][1]);
            // pass 2: Ahi*Blo (kstep4 adds bias_lo)
#pragma unroll
            for (int ks = 0; ks < 5; ++ks)
                mma_tf32(c0,c1,c2,c3, ahi[ks][0],ahi[ks][1],ahi[ks][2],ahi[ks][3],
                         blo[ks][0], blo[ks][1]);
            // pass 3: Alo*Bhi (ksteps 0..3)
#pragma unroll
            for (int ks = 0; ks < 4; ++ks)
                mma_tf32(c0,c1,c2,c3, alo[ks][0],alo[ks][1],alo[ks][2],alo[ks][3],
                         bhi[ks][0], bhi[ks][1]);

            // argmax update: c0,c1 -> row r0; c2,c3 -> row r1; cols n0, n0+1
            const int n0 = t * SCODES + ch * 8 + tg * 2;
            if (c0 > best0) { best0 = c0; bi0 = n0;     }
            if (c1 > best0) { best0 = c1; bi0 = n0 + 1; }
            if (c2 > best1) { best1 = c2; bi1 = n0;     }
            if (c3 > best1) { best1 = c3; bi1 = n0 + 1; }
        }
        __syncthreads();   // stage slot free before next issue overwrites it
    }

    // ---- cross-lane reduce over the 4 tg lanes (min-index tie-break) ----
#pragma unroll
    for (int off = 1; off < 4; off <<= 1) {
        float ob0 = __shfl_xor_sync(0xffffffffu, best0, off);
        int   oi0 = __shfl_xor_sync(0xffffffffu, bi0,   off);
        float ob1 = __shfl_xor_sync(0xffffffffu, best1, off);
        int   oi1 = __shfl_xor_sync(0xffffffffu, bi1,   off);
        if (ob0 > best0 || (ob0 == best0 && oi0 < bi0)) { best0 = ob0; bi0 = oi0; }
        if (ob1 > best1 || (ob1 == best1 && oi1 < bi1)) { best1 = ob1; bi1 = oi1; }
    }

    // ---- outputs + loss partial ----
    float lsum = 0.0f;
    if (tg == 0) {
        idx_out[r0] = (float)bi0;
        idx_out[r1] = (float)bi1;
        const int rows[2] = { r0, r1 };
        const int bis[2]  = { bi0, bi1 };
#pragma unroll
        for (int k = 0; k < 2; ++k) {
            const int r = rows[k], b = bis[k];
            const float4* e4 = reinterpret_cast<const float4*>(g_codes_norm + (size_t)b * D_DIM);
            float4* oq = reinterpret_cast<float4*>(zq_out + (size_t)r * D_DIM);
            const float* ah = g_ahi + (size_t)r * ASTRIDE;
            const float* al = g_alo + (size_t)r * ASTRIDE;
#pragma unroll
            for (int i = 0; i < 8; ++i) {
                float4 q = e4[i];
                float qs[4] = { q.x, q.y, q.z, q.w };
#pragma unroll
                for (int j = 0; j < 4; ++j) {
                    float zn = ah[4*i+j] + al[4*i+j];
                    float d  = qs[j] - zn;
                    lsum += d * d;
                }
                oq[i] = q;
            }
        }
    }
    float* red = reinterpret_cast<float*>(smem + SMEM_B);
    red[tid] = lsum;
    __syncthreads();
    if (tid == 0) {
        float s = 0.0f;
        for (int i = 0; i < NTHR; ++i) s += red[i];
        g_partial[rb] = s;
    }
}

// ---------------- finalize loss ----------------
__global__ void vq_finalize(float* __restrict__ loss_out) {
    float s = 0.0f;
    for (int i = 0; i < GRID_MAIN; ++i) s += g_partial[i];
    loss_out[0] = 1.25f * s / (float)(N_ROWS * D_DIM);
}

// ---------------- launch ----------------
extern "C" void kernel_launch(void* const* d_in, const int* in_sizes, int n_in,
                              void* d_out, int out_size) {
    const float* z   = (const float*)d_in[0];   // [32,1024,32]
    const float* emb = (const float*)d_in[1];   // [8192,32]
    float* out = (float*)d_out;

    float* zq_out   = out;                               // 1048576 floats
    float* loss_out = out + (size_t)N_ROWS * D_DIM;      // 1 float
    float* idx_out  = loss_out + 1;                      // 32768 floats

    cudaFuncSetAttribute(vq_main, cudaFuncAttributeMaxDynamicSharedMemorySize, SMEM_TOTAL);

    vq_prep_z<<<N_ROWS / 256, 256>>>(z);
    vq_prep_codes<<<K_CODES / 256, 256>>>(emb);
    vq_main<<<GRID_MAIN, NTHR, SMEM_TOTAL>>>(zq_out, idx_out);
    vq_finalize<<<1, 1>>>(loss_out);
}

// round 4
// speedup vs baseline: 3.7560x; 2.2685x over previous
#include <cuda_runtime.h>
#include <cuda_fp16.h>
#include <cstdint>
#include <math.h>

// ---------------- problem constants ----------------
#define D_DIM     32
#define K_CODES   8192
#define N_ROWS    32768
#define MROWS     128                 // rows per CTA
#define GRID_MAIN (N_ROWS / MROWS)    // 256
#define NTHR      256                 // 8 warps
#define SCODES    256                 // codes per pipeline stage
#define NSTAGES   (K_CODES / SCODES)  // 32
#define NCHUNK    (SCODES / 8)        // 32 chunks of 8 codes

// stage layout: [hi 16384 B][lo 16384 B][bias 1024 B] = 33792 B
#define ST_HI     0
#define ST_LO     16384
#define ST_BIAS   32768
#define STAGE_BYTES 33792
#define STAGE_U16   (STAGE_BYTES / 16)       // 2112
#define SMEM_RED    (2 * STAGE_BYTES)        // 67584
#define SMEM_TOTAL  (SMEM_RED + NTHR * 4)    // 68608

// ---------------- device globals (no cudaMalloc allowed) ----------------
__device__ __align__(1024) uint32_t g_ah2[N_ROWS * 16];       // z hi, half2 packed [row][k2]
__device__ __align__(1024) uint32_t g_al2[N_ROWS * 16];       // z lo
__device__ __align__(1024) char     g_bpack[NSTAGES * STAGE_BYTES]; // fragment-packed codes
__device__ __align__(16)   float    g_codes_norm[K_CODES * D_DIM];
__device__ __align__(16)   float    g_znorm[N_ROWS * D_DIM];
__device__ float g_partial[GRID_MAIN];

// ---------------- helpers ----------------
static __device__ __forceinline__ uint32_t smem_u32(const void* p) {
    uint32_t a;
    asm("{ .reg .u64 t; cvta.to.shared.u64 t, %1; cvt.u32.u64 %0, t; }" : "=r"(a) : "l"(p));
    return a;
}
#define CP_ASYNC16(dst, src) \
    asm volatile("cp.async.cg.shared.global [%0], [%1], 16;" :: "r"(dst), "l"(src) : "memory")
#define CP_COMMIT() asm volatile("cp.async.commit_group;" ::: "memory")
#define CP_WAIT(n)  asm volatile("cp.async.wait_group %0;" :: "n"(n) : "memory")

static __device__ __forceinline__ void mma_f16(float& c0, float& c1, float& c2, float& c3,
                                               uint32_t a0, uint32_t a1, uint32_t a2, uint32_t a3,
                                               uint32_t b0, uint32_t b1) {
    asm volatile("mma.sync.aligned.m16n8k16.row.col.f32.f16.f16.f32 "
                 "{%0,%1,%2,%3}, {%4,%5,%6,%7}, {%8,%9}, {%0,%1,%2,%3};"
                 : "+f"(c0), "+f"(c1), "+f"(c2), "+f"(c3)
                 : "r"(a0), "r"(a1), "r"(a2), "r"(a3), "r"(b0), "r"(b1));
}
static __device__ __forceinline__ uint32_t pack_h2(float x, float y) {
    __half2 h = __floats2half2_rn(x, y);
    return *reinterpret_cast<uint32_t*>(&h);
}

// ---------------- prep: normalize z rows, fp16 split, pack ----------------
__global__ void vq_prep_z(const float* __restrict__ z) {
    int row = blockIdx.x * blockDim.x + threadIdx.x;   // 32768 threads
    const float4* zp = reinterpret_cast<const float4*>(z + (size_t)row * D_DIM);
    float v[D_DIM]; float ss = 0.0f;
#pragma unroll
    for (int i = 0; i < 8; ++i) {
        float4 q = zp[i];
        v[4*i+0]=q.x; v[4*i+1]=q.y; v[4*i+2]=q.z; v[4*i+3]=q.w;
        ss += q.x*q.x + q.y*q.y + q.z*q.z + q.w*q.w;
    }
    float inv = 1.0f / fmaxf(sqrtf(ss), 1e-12f);
    float hi[D_DIM], lo[D_DIM];
#pragma unroll
    for (int c = 0; c < D_DIM; ++c) {
        float x = v[c] * inv;
        g_znorm[(size_t)row * D_DIM + c] = x;
        float h = __half2float(__float2half_rn(x));
        hi[c] = h;
        lo[c] = x - h;
    }
    uint32_t* ah = g_ah2 + (size_t)row * 16;
    uint32_t* al = g_al2 + (size_t)row * 16;
#pragma unroll
    for (int k2 = 0; k2 < 16; ++k2) {
        ah[k2] = pack_h2(hi[2*k2], hi[2*k2+1]);
        al[k2] = pack_h2(lo[2*k2], lo[2*k2+1]);
    }
}

// ---------------- prep: normalize codes, fp16 split, fragment-pack ----------------
__global__ void vq_prep_codes(const float* __restrict__ emb) {
    int t = blockIdx.x * blockDim.x + threadIdx.x;     // 8192 threads
    const float4* ep = reinterpret_cast<const float4*>(emb + (size_t)t * D_DIM);
    float v[D_DIM]; float ss = 0.0f;
#pragma unroll
    for (int i = 0; i < 8; ++i) {
        float4 q = ep[i];
        v[4*i+0]=q.x; v[4*i+1]=q.y; v[4*i+2]=q.z; v[4*i+3]=q.w;
        ss += q.x*q.x + q.y*q.y + q.z*q.z + q.w*q.w;
    }
    float inv = 1.0f / fmaxf(sqrtf(ss), 1e-12f);
    float hi[D_DIM], lo[D_DIM];
    float ss2 = 0.0f;
#pragma unroll
    for (int c = 0; c < D_DIM; ++c) {
        float x = v[c] * inv;
        g_codes_norm[(size_t)t * D_DIM + c] = x;
        ss2 += x * x;
        float h = __half2float(__float2half_rn(x));
        hi[c] = h;
        lo[c] = x - h;
    }
    const int tile = t >> 8, ci = t & 255;
    char* base = g_bpack + (size_t)tile * STAGE_BYTES;
    uint32_t* bh = reinterpret_cast<uint32_t*>(base + ST_HI + ci * 64);
    uint32_t* bl = reinterpret_cast<uint32_t*>(base + ST_LO + ci * 64);
    // perm: dst slot i = tg*4+j  <-  src k2 = tg + 4j   (makes per-lane LDS.128)
#pragma unroll
    for (int i = 0; i < 16; ++i) {
        int tg = i >> 2, j = i & 3;
        int k2 = tg + 4 * j;
        bh[i] = pack_h2(hi[2*k2], hi[2*k2+1]);
        bl[i] = pack_h2(lo[2*k2], lo[2*k2+1]);
    }
    reinterpret_cast<float*>(base + ST_BIAS)[ci] = -0.5f * ss2;  // per-code bias (rounding jitter)
}

// ---------------- main: 3xFP16 mma.sync GEMM + fused argmax ----------------
__global__ void __launch_bounds__(NTHR, 2)
vq_main(float* __restrict__ zq_out, float* __restrict__ idx_out) {
    extern __shared__ __align__(16) char smem[];
    const uint32_t sb = smem_u32(smem);
    const int tid = threadIdx.x;
    const int w   = tid >> 5;          // warp 0..7
    const int g   = (tid & 31) >> 2;   // group 0..7
    const int tg  = tid & 3;           // thread-in-group
    const int rb  = blockIdx.x;

    const int r0 = rb * MROWS + w * 16 + g;
    const int r1 = r0 + 8;

    // resident A fragments: 2 ksteps x 4 regs, hi and lo
    uint32_t ahi[2][4], alo[2][4];
    {
        const uint32_t* A0 = g_ah2 + (size_t)r0 * 16;
        const uint32_t* A1 = g_ah2 + (size_t)r1 * 16;
        const uint32_t* L0 = g_al2 + (size_t)r0 * 16;
        const uint32_t* L1 = g_al2 + (size_t)r1 * 16;
#pragma unroll
        for (int ks = 0; ks < 2; ++ks) {
            ahi[ks][0] = A0[ks*8 + tg];     ahi[ks][1] = A1[ks*8 + tg];
            ahi[ks][2] = A0[ks*8 + tg + 4]; ahi[ks][3] = A1[ks*8 + tg + 4];
            alo[ks][0] = L0[ks*8 + tg];     alo[ks][1] = L1[ks*8 + tg];
            alo[ks][2] = L0[ks*8 + tg + 4]; alo[ks][3] = L1[ks*8 + tg + 4];
        }
    }

    auto stage_copy = [&](int t) {
        const int slot = t & 1;
        const char* src = g_bpack + (size_t)t * STAGE_BYTES;
        const uint32_t dst = sb + slot * STAGE_BYTES;
#pragma unroll
        for (int j = 0; j < 8; ++j) {
            int u = tid + j * NTHR;            // 0..2047
            CP_ASYNC16(dst + u * 16, src + (size_t)u * 16);
        }
        if (tid < STAGE_U16 - 2048)
            CP_ASYNC16(dst + (2048 + tid) * 16, src + (size_t)(2048 + tid) * 16);
        CP_COMMIT();
    };

    float best0 = -1e30f, best1 = -1e30f;
    int   bi0 = 0, bi1 = 0;

    stage_copy(0);
    for (int t = 0; t < NSTAGES; ++t) {
        if (t + 1 < NSTAGES) { stage_copy(t + 1); CP_WAIT(1); }
        else                 { CP_WAIT(0); }
        __syncthreads();

        const char* st = smem + (t & 1) * STAGE_BYTES;
        const int base = t * SCODES;

#pragma unroll 2
        for (int ch = 0; ch < NCHUNK; ++ch) {
            const int code0 = ch * 8 + g;
            uint4 H = *reinterpret_cast<const uint4*>(st + ST_HI + code0 * 64 + tg * 16);
            uint4 L = *reinterpret_cast<const uint4*>(st + ST_LO + code0 * 64 + tg * 16);
            float2 bb = *reinterpret_cast<const float2*>(st + ST_BIAS + (ch * 8 + 2 * tg) * 4);

            float c0 = bb.x, c1 = bb.y, c2 = bb.x, c3 = bb.y;  // bias as accumulator init
            // pass 1: Ahi * Bhi
            mma_f16(c0,c1,c2,c3, ahi[0][0],ahi[0][1],ahi[0][2],ahi[0][3], H.x, H.y);
            mma_f16(c0,c1,c2,c3, ahi[1][0],ahi[1][1],ahi[1][2],ahi[1][3], H.z, H.w);
            // pass 2: Ahi * Blo
            mma_f16(c0,c1,c2,c3, ahi[0][0],ahi[0][1],ahi[0][2],ahi[0][3], L.x, L.y);
            mma_f16(c0,c1,c2,c3, ahi[1][0],ahi[1][1],ahi[1][2],ahi[1][3], L.z, L.w);
            // pass 3: Alo * Bhi
            mma_f16(c0,c1,c2,c3, alo[0][0],alo[0][1],alo[0][2],alo[0][3], H.x, H.y);
            mma_f16(c0,c1,c2,c3, alo[1][0],alo[1][1],alo[1][2],alo[1][3], H.z, H.w);

            const int n0 = base + ch * 8 + 2 * tg;
            if (c0 > best0) { best0 = c0; bi0 = n0;     }
            if (c1 > best0) { best0 = c1; bi0 = n0 + 1; }
            if (c2 > best1) { best1 = c2; bi1 = n0;     }
            if (c3 > best1) { best1 = c3; bi1 = n0 + 1; }
        }
        __syncthreads();
    }

    // reduce over the 4 tg lanes (min-index tie-break)
#pragma unroll
    for (int off = 1; off < 4; off <<= 1) {
        float ob0 = __shfl_xor_sync(0xffffffffu, best0, off);
        int   oi0 = __shfl_xor_sync(0xffffffffu, bi0,   off);
        float ob1 = __shfl_xor_sync(0xffffffffu, best1, off);
        int   oi1 = __shfl_xor_sync(0xffffffffu, bi1,   off);
        if (ob0 > best0 || (ob0 == best0 && oi0 < bi0)) { best0 = ob0; bi0 = oi0; }
        if (ob1 > best1 || (ob1 == best1 && oi1 < bi1)) { best1 = ob1; bi1 = oi1; }
    }

    // ---- outputs + loss partial ----
    float lsum = 0.0f;
    if (tg == 0) {
        idx_out[r0] = (float)bi0;
        idx_out[r1] = (float)bi1;
        const int rows[2] = { r0, r1 };
        const int bis[2]  = { bi0, bi1 };
#pragma unroll
        for (int k = 0; k < 2; ++k) {
            const int r = rows[k], b = bis[k];
            const float4* e4 = reinterpret_cast<const float4*>(g_codes_norm + (size_t)b * D_DIM);
            const float4* z4 = reinterpret_cast<const float4*>(g_znorm + (size_t)r * D_DIM);
            float4* oq = reinterpret_cast<float4*>(zq_out + (size_t)r * D_DIM);
#pragma unroll
            for (int i = 0; i < 8; ++i) {
                float4 q = e4[i];
                float4 zn = z4[i];
                float d0 = q.x - zn.x, d1 = q.y - zn.y, d2 = q.z - zn.z, d3 = q.w - zn.w;
                lsum += d0*d0 + d1*d1 + d2*d2 + d3*d3;
                oq[i] = q;
            }
        }
    }
    float* red = reinterpret_cast<float*>(smem + SMEM_RED);
    red[tid] = lsum;
    __syncthreads();
    if (tid == 0) {
        float s = 0.0f;
        for (int i = 0; i < NTHR; ++i) s += red[i];
        g_partial[rb] = s;
    }
}

// ---------------- finalize loss ----------------
__global__ void vq_finalize(float* __restrict__ loss_out) {
    float s = 0.0f;
    for (int i = 0; i < GRID_MAIN; ++i) s += g_partial[i];
    loss_out[0] = 1.25f * s / (float)(N_ROWS * D_DIM);
}

// ---------------- launch ----------------
extern "C" void kernel_launch(void* const* d_in, const int* in_sizes, int n_in,
                              void* d_out, int out_size) {
    const float* z   = (const float*)d_in[0];   // [32,1024,32]
    const float* emb = (const float*)d_in[1];   // [8192,32]
    float* out = (float*)d_out;

    float* zq_out   = out;                               // 1048576 floats
    float* loss_out = out + (size_t)N_ROWS * D_DIM;      // 1 float
    float* idx_out  = loss_out + 1;                      // 32768 floats

    cudaFuncSetAttribute(vq_main, cudaFuncAttributeMaxDynamicSharedMemorySize, SMEM_TOTAL);

    vq_prep_z<<<N_ROWS / 256, 256>>>(z);
    vq_prep_codes<<<K_CODES / 256, 256>>>(emb);
    vq_main<<<GRID_MAIN, NTHR, SMEM_TOTAL>>>(zq_out, idx_out);
    vq_finalize<<<1, 1>>>(loss_out);
}